// round 14
// baseline (speedup 1.0000x reference)
#include <cuda_runtime.h>
#include <cuda_bf16.h>
#include <cuda_fp8.h>
#include <cstdint>

// Problem shape (static per metadata)
#define MDIM 32768L
#define NDIM 2048L
#define KDIM 2048L

// GEMM tiling (mma.sync m16n8k32 e4m3 path)
#define BM 128
#define BN 128
#define BK 64
#define KTILES 32            // KDIM / BK
#define ASTRIDE 80           // 64 data bytes + 16 pad: 16B-aligned, LDS conflict-free
#define OP_BYTES (128 * ASTRIDE)        // 10240 per operand per stage
#define STAGE_BYTES (2 * OP_BYTES)      // 20480
#define SMEM_BYTES (3 * STAGE_BYTES + 256)  // + bias cache

// -------------------- device scratch (static; no runtime allocation) ------
__device__ unsigned g_amax[2];   // f32 bits of amax(|x|), amax(|w|)
__device__ __align__(128) __nv_bfloat16 g_bias[NDIM];
__device__ __align__(128) unsigned char g_xq[(size_t)MDIM * KDIM];  // 64 MB fp8
__device__ __align__(128) unsigned char g_wq[(size_t)NDIM * KDIM];  //  4 MB fp8

// -------------------- kernels ---------------------------------------------
__global__ void reset_kernel() { g_amax[0] = 0u; g_amax[1] = 0u; }

// amax over f32 tensor (values are bf16-exact). abs via bit mask; int-compare
// on positive floats == float compare.
__global__ void amax_f32(const uint4* __restrict__ p, long n_vec4, int slot) {
    unsigned m = 0;
    long stride = (long)gridDim.x * blockDim.x;
    for (long i = (long)blockIdx.x * blockDim.x + threadIdx.x; i < n_vec4; i += stride) {
        uint4 v = p[i];
        m = max(m, v.x & 0x7FFFFFFFu);
        m = max(m, v.y & 0x7FFFFFFFu);
        m = max(m, v.z & 0x7FFFFFFFu);
        m = max(m, v.w & 0x7FFFFFFFu);
    }
    m = __reduce_max_sync(0xFFFFFFFFu, m);
    __shared__ unsigned sred[8];
    int wid = threadIdx.x >> 5;
    if ((threadIdx.x & 31) == 0) sred[wid] = m;
    __syncthreads();
    if (threadIdx.x == 0) {
        unsigned mm = 0;
        int nw = blockDim.x >> 5;
        for (int i = 0; i < nw; i++) mm = max(mm, sred[i]);
        atomicMax(&g_amax[slot], mm);
    }
}

// quantize f32 -> e4m3 (RN, satfinite), scale = max(amax, 1e-6). 8 floats/iter.
__global__ void quant_f32(const uint4* __restrict__ src, uint2* __restrict__ dst,
                          long n, int slot) {
    float s = fmaxf(__uint_as_float(g_amax[slot]), 1e-6f);
    long stride = (long)gridDim.x * blockDim.x;
    long iters = n / 8;
    for (long i = (long)blockIdx.x * blockDim.x + threadIdx.x; i < iters; i += stride) {
        uint4 v0 = src[2 * i], v1 = src[2 * i + 1];
        float2 f[4];
        f[0] = make_float2(__uint_as_float(v0.x), __uint_as_float(v0.y));
        f[1] = make_float2(__uint_as_float(v0.z), __uint_as_float(v0.w));
        f[2] = make_float2(__uint_as_float(v1.x), __uint_as_float(v1.y));
        f[3] = make_float2(__uint_as_float(v1.z), __uint_as_float(v1.w));
        unsigned short q[4];
#pragma unroll
        for (int j = 0; j < 4; j++) {
            f[j].x = __fdiv_rn(f[j].x, s);
            f[j].y = __fdiv_rn(f[j].y, s);
            q[j] = __nv_cvt_float2_to_fp8x2(f[j], __NV_SATFINITE, __NV_E4M3);
        }
        uint2 o;
        o.x = (unsigned)q[0] | ((unsigned)q[1] << 16);
        o.y = (unsigned)q[2] | ((unsigned)q[3] << 16);
        dst[i] = o;
    }
}

// bias: f32 (bf16-exact values) -> bf16 staging (conversion exact)
__global__ void bias_prep(const float* __restrict__ bias) {
    int i = blockIdx.x * blockDim.x + threadIdx.x;  // 0..2047
    g_bias[i] = __float2bfloat16(bias[i]);
}

// -------------------- mma.sync fp8 GEMM ------------------------------------
__device__ __forceinline__ void cpasync16(uint32_t dst, const void* src) {
    asm volatile("cp.async.cg.shared.global [%0], [%1], 16;\n"
                 :: "r"(dst), "l"(src));
}

__device__ __forceinline__ void mma_e4m3(float* d, const uint32_t* a,
                                         uint32_t b0, uint32_t b1) {
    asm volatile(
        "mma.sync.aligned.m16n8k32.row.col.f32.e4m3.e4m3.f32 "
        "{%0,%1,%2,%3}, {%4,%5,%6,%7}, {%8,%9}, {%0,%1,%2,%3};\n"
        : "+f"(d[0]), "+f"(d[1]), "+f"(d[2]), "+f"(d[3])
        : "r"(a[0]), "r"(a[1]), "r"(a[2]), "r"(a[3]), "r"(b0), "r"(b1));
}

// D[128,128] per CTA. 256 threads = 8 warps: mw = wid&3 (32 M-rows each),
// nw = wid>>2 (64 N-cols each). 3-stage cp.async pipeline, BK=64.
// OUTPUT FLOAT32: f32( bf16(acc*xs*ws) + bias_bf16 ).
__global__ void __launch_bounds__(256, 2) gemm_kernel(
    const unsigned char* __restrict__ xq,
    const unsigned char* __restrict__ wq,
    float* __restrict__ out)
{
    extern __shared__ unsigned char sm[];
    const int tid = threadIdx.x;
    const int wid = tid >> 5;
    const int lane = tid & 31;
    const int mw = wid & 3;
    const int nw = wid >> 2;
    const long m0 = (long)blockIdx.y * BM;
    const int  n0 = blockIdx.x * BN;

    uint32_t sb;
    asm("{ .reg .u64 t; cvta.to.shared.u64 t, %1; cvt.u32.u64 %0, t; }"
        : "=r"(sb) : "l"(sm));

    // bias cache (128 bf16 at offset 3*STAGE_BYTES)
    __nv_bfloat16* biasSm = reinterpret_cast<__nv_bfloat16*>(sm + 3 * STAGE_BYTES);
    if (tid < 64)
        reinterpret_cast<uint32_t*>(biasSm)[tid] =
            reinterpret_cast<const uint32_t*>(g_bias + n0)[tid];

    // stage loader: A tile rows m0..m0+127, B tile rows n0..n0+127, cols k0..k0+63
    auto load_stage = [&](int s, int k0) {
#pragma unroll
        for (int c = tid; c < 1024; c += 256) {
            int isB = c >> 9;
            int cc  = c & 511;
            int row = cc >> 2;
            int seg = cc & 3;
            const unsigned char* g = isB
                ? wq + (size_t)(n0 + row) * KDIM + k0 + seg * 16
                : xq + (size_t)(m0 + row) * KDIM + k0 + seg * 16;
            uint32_t d = sb + (uint32_t)s * STAGE_BYTES + (uint32_t)isB * OP_BYTES
                       + (uint32_t)row * ASTRIDE + (uint32_t)seg * 16;
            cpasync16(d, g);
        }
    };

    float acc[2][8][4];
#pragma unroll
    for (int mt = 0; mt < 2; mt++)
#pragma unroll
        for (int nt = 0; nt < 8; nt++)
#pragma unroll
            for (int j = 0; j < 4; j++) acc[mt][nt][j] = 0.0f;

    // prologue: stages 0,1
    load_stage(0, 0);
    asm volatile("cp.async.commit_group;\n" ::: "memory");
    load_stage(1, BK);
    asm volatile("cp.async.commit_group;\n" ::: "memory");

    const int r8 = lane >> 2;       // 0..7
    const int kq = (lane & 3) * 4;  // 0,4,8,12

#pragma unroll 1
    for (int kt = 0; kt < KTILES; kt++) {
        asm volatile("cp.async.wait_group 1;\n" ::: "memory");
        __syncthreads();

        int kn = kt + 2;
        if (kn < KTILES) load_stage(kn % 3, kn * BK);
        asm volatile("cp.async.commit_group;\n" ::: "memory");

        const unsigned char* aS = sm + (kt % 3) * STAGE_BYTES;
        const unsigned char* bS = aS + OP_BYTES;

#pragma unroll
        for (int ks = 0; ks < 2; ks++) {
            const int kb = ks * 32 + kq;
            uint32_t a[2][4];
#pragma unroll
            for (int mt = 0; mt < 2; mt++) {
                const unsigned char* ap = aS + (mw * 32 + mt * 16 + r8) * ASTRIDE + kb;
                a[mt][0] = *reinterpret_cast<const uint32_t*>(ap);
                a[mt][1] = *reinterpret_cast<const uint32_t*>(ap + 8 * ASTRIDE);
                a[mt][2] = *reinterpret_cast<const uint32_t*>(ap + 16);
                a[mt][3] = *reinterpret_cast<const uint32_t*>(ap + 8 * ASTRIDE + 16);
            }
#pragma unroll
            for (int nt = 0; nt < 8; nt++) {
                const unsigned char* bp = bS + (nw * 64 + nt * 8 + r8) * ASTRIDE + kb;
                uint32_t b0 = *reinterpret_cast<const uint32_t*>(bp);
                uint32_t b1 = *reinterpret_cast<const uint32_t*>(bp + 16);
                mma_e4m3(acc[0][nt], a[0], b0, b1);
                mma_e4m3(acc[1][nt], a[1], b0, b1);
            }
        }
    }

    // -------- epilogue: scale, bf16 round, +bias (bf16 add), widen to f32 ----
    float xs = fmaxf(__uint_as_float(g_amax[0]), 1e-6f);
    float ws = fmaxf(__uint_as_float(g_amax[1]), 1e-6f);
    float sc = xs * ws;

#pragma unroll
    for (int mt = 0; mt < 2; mt++) {
        long r0 = m0 + mw * 32 + mt * 16 + r8;
#pragma unroll
        for (int nt = 0; nt < 8; nt++) {
            int cn = nw * 64 + nt * 8 + (lane & 3) * 2;  // local col in [0,128)
            long g0 = r0 * NDIM + n0 + cn;
            long g1 = (r0 + 8) * NDIM + n0 + cn;
            __nv_bfloat16 v00 = __hadd(__float2bfloat16(acc[mt][nt][0] * sc), biasSm[cn]);
            __nv_bfloat16 v01 = __hadd(__float2bfloat16(acc[mt][nt][1] * sc), biasSm[cn + 1]);
            __nv_bfloat16 v10 = __hadd(__float2bfloat16(acc[mt][nt][2] * sc), biasSm[cn]);
            __nv_bfloat16 v11 = __hadd(__float2bfloat16(acc[mt][nt][3] * sc), biasSm[cn + 1]);
            float2 f0 = make_float2(__bfloat162float(v00), __bfloat162float(v01));
            float2 f1 = make_float2(__bfloat162float(v10), __bfloat162float(v11));
            *reinterpret_cast<float2*>(out + g0) = f0;
            *reinterpret_cast<float2*>(out + g1) = f1;
        }
    }
}

// -------------------- host side -------------------------------------------
extern "C" void kernel_launch(void* const* d_in, const int* in_sizes, int n_in,
                              void* d_out, int out_size) {
    // Resolve inputs BY SIZE (element counts): x=M*K, weight=N*K, bias=N.
    // All buffers are FLOAT32 (bf16 values widened by the harness).
    const float* x = nullptr;
    const float* w = nullptr;
    const float* bias = nullptr;
    for (int i = 0; i < n_in; i++) {
        long sz = in_sizes[i];
        if (sz == MDIM * KDIM)      x    = (const float*)d_in[i];
        else if (sz == NDIM * KDIM) w    = (const float*)d_in[i];
        else if (sz == NDIM)        bias = (const float*)d_in[i];
    }
    float* out = (float*)d_out;

    void *xq = nullptr, *wq = nullptr;
    cudaGetSymbolAddress(&xq, g_xq);
    cudaGetSymbolAddress(&wq, g_wq);

    // 1) reset
    reset_kernel<<<1, 1>>>();
    // 2) amax (f32 reads)
    amax_f32<<<2048, 256>>>((const uint4*)x, MDIM * KDIM / 4, 0);
    amax_f32<<<512, 256>>>((const uint4*)w, NDIM * KDIM / 4, 1);
    // 3) quantize f32 -> e4m3 scratch
    quant_f32<<<4096, 256>>>((const uint4*)x, (uint2*)xq, MDIM * KDIM, 0);
    quant_f32<<<1024, 256>>>((const uint4*)w, (uint2*)wq, NDIM * KDIM, 1);
    // 4) bias staging (f32 -> bf16, exact)
    bias_prep<<<2, 1024>>>(bias);

    // 5) GEMM (mma.sync fp8; f32 output)
    cudaFuncSetAttribute(gemm_kernel, cudaFuncAttributeMaxDynamicSharedMemorySize,
                         SMEM_BYTES);
    dim3 grid((unsigned)(NDIM / BN), (unsigned)(MDIM / BM), 1);
    gemm_kernel<<<grid, 256, SMEM_BYTES>>>(
        (const unsigned char*)xq, (const unsigned char*)wq, out);
}

// round 15
// speedup vs baseline: 1.0851x; 1.0851x over previous
#include <cuda_runtime.h>
#include <cuda_bf16.h>
#include <cuda_fp8.h>
#include <cstdint>

// Problem shape (static per metadata)
#define MDIM 32768L
#define NDIM 2048L
#define KDIM 2048L

// GEMM tiling (mma.sync m16n8k32 e4m3 path)
#define BM 128
#define BN 128
#define BK 64
#define KTILES 32            // KDIM / BK
#define STAGES 4
#define PREFETCH 3
#define ASTRIDE 80           // 64 data bytes + 16 pad: 16B-aligned, ldmatrix conflict-free
#define OP_BYTES (128 * ASTRIDE)        // 10240 per operand per stage
#define STAGE_BYTES (2 * OP_BYTES)      // 20480
#define SMEM_BYTES (STAGES * STAGE_BYTES + 256)  // + bias cache

// -------------------- device scratch (static; no runtime allocation) ------
__device__ unsigned g_amax[2];   // f32 bits of amax(|x|), amax(|w|)
__device__ __align__(128) __nv_bfloat16 g_bias[NDIM];
__device__ __align__(128) unsigned char g_xq[(size_t)MDIM * KDIM];  // 64 MB fp8
__device__ __align__(128) unsigned char g_wq[(size_t)NDIM * KDIM];  //  4 MB fp8

// -------------------- kernels ---------------------------------------------
__global__ void reset_kernel() { g_amax[0] = 0u; g_amax[1] = 0u; }

// amax over f32 tensor (values are bf16-exact). abs via bit mask; int-compare
// on positive floats == float compare.
__global__ void amax_f32(const uint4* __restrict__ p, long n_vec4, int slot) {
    unsigned m = 0;
    long stride = (long)gridDim.x * blockDim.x;
    for (long i = (long)blockIdx.x * blockDim.x + threadIdx.x; i < n_vec4; i += stride) {
        uint4 v = p[i];
        m = max(m, v.x & 0x7FFFFFFFu);
        m = max(m, v.y & 0x7FFFFFFFu);
        m = max(m, v.z & 0x7FFFFFFFu);
        m = max(m, v.w & 0x7FFFFFFFu);
    }
    m = __reduce_max_sync(0xFFFFFFFFu, m);
    __shared__ unsigned sred[8];
    int wid = threadIdx.x >> 5;
    if ((threadIdx.x & 31) == 0) sred[wid] = m;
    __syncthreads();
    if (threadIdx.x == 0) {
        unsigned mm = 0;
        int nw = blockDim.x >> 5;
        for (int i = 0; i < nw; i++) mm = max(mm, sred[i]);
        atomicMax(&g_amax[slot], mm);
    }
}

// quantize f32 -> e4m3 (RN, satfinite), scale = max(amax, 1e-6). 16 floats/iter.
__global__ void quant_f32(const uint4* __restrict__ src, uint4* __restrict__ dst,
                          long n, int slot) {
    float s = fmaxf(__uint_as_float(g_amax[slot]), 1e-6f);
    long stride = (long)gridDim.x * blockDim.x;
    long iters = n / 16;
    for (long i = (long)blockIdx.x * blockDim.x + threadIdx.x; i < iters; i += stride) {
        unsigned q8[4];
#pragma unroll
        for (int h = 0; h < 2; h++) {
            uint4 v0 = src[4 * i + 2 * h], v1 = src[4 * i + 2 * h + 1];
            float2 f[4];
            f[0] = make_float2(__uint_as_float(v0.x), __uint_as_float(v0.y));
            f[1] = make_float2(__uint_as_float(v0.z), __uint_as_float(v0.w));
            f[2] = make_float2(__uint_as_float(v1.x), __uint_as_float(v1.y));
            f[3] = make_float2(__uint_as_float(v1.z), __uint_as_float(v1.w));
            unsigned short q[4];
#pragma unroll
            for (int j = 0; j < 4; j++) {
                f[j].x = __fdiv_rn(f[j].x, s);
                f[j].y = __fdiv_rn(f[j].y, s);
                q[j] = __nv_cvt_float2_to_fp8x2(f[j], __NV_SATFINITE, __NV_E4M3);
            }
            q8[2 * h + 0] = (unsigned)q[0] | ((unsigned)q[1] << 16);
            q8[2 * h + 1] = (unsigned)q[2] | ((unsigned)q[3] << 16);
        }
        uint4 o;
        o.x = q8[0]; o.y = q8[1]; o.z = q8[2]; o.w = q8[3];
        dst[i] = o;
    }
}

// bias: f32 (bf16-exact values) -> bf16 staging (conversion exact)
__global__ void bias_prep(const float* __restrict__ bias) {
    int i = blockIdx.x * blockDim.x + threadIdx.x;  // 0..2047
    g_bias[i] = __float2bfloat16(bias[i]);
}

// -------------------- mma.sync fp8 GEMM ------------------------------------
__device__ __forceinline__ void cpasync16(uint32_t dst, const void* src) {
    asm volatile("cp.async.cg.shared.global [%0], [%1], 16;\n"
                 :: "r"(dst), "l"(src));
}

__device__ __forceinline__ void mma_e4m3(float* d, const uint32_t* a,
                                         uint32_t b0, uint32_t b1) {
    asm volatile(
        "mma.sync.aligned.m16n8k32.row.col.f32.e4m3.e4m3.f32 "
        "{%0,%1,%2,%3}, {%4,%5,%6,%7}, {%8,%9}, {%0,%1,%2,%3};\n"
        : "+f"(d[0]), "+f"(d[1]), "+f"(d[2]), "+f"(d[3])
        : "r"(a[0]), "r"(a[1]), "r"(a[2]), "r"(a[3]), "r"(b0), "r"(b1));
}

__device__ __forceinline__ void ldsm_x4(uint32_t addr, uint32_t& r0, uint32_t& r1,
                                        uint32_t& r2, uint32_t& r3) {
    asm volatile("ldmatrix.sync.aligned.m8n8.x4.shared.b16 {%0,%1,%2,%3}, [%4];\n"
                 : "=r"(r0), "=r"(r1), "=r"(r2), "=r"(r3) : "r"(addr));
}

// D[128,128] per CTA. 256 threads = 8 warps: mw = wid&3 (32 M-rows each),
// nw = wid>>2 (64 N-cols each). 4-stage cp.async pipeline, BK=64, ldmatrix frags.
// OUTPUT FLOAT32: f32( bf16(acc*xs*ws) + bias_bf16 ).
__global__ void __launch_bounds__(256, 2) gemm_kernel(
    const unsigned char* __restrict__ xq,
    const unsigned char* __restrict__ wq,
    float* __restrict__ out)
{
    extern __shared__ unsigned char sm[];
    const int tid = threadIdx.x;
    const int wid = tid >> 5;
    const int lane = tid & 31;
    const int mw = wid & 3;
    const int nw = wid >> 2;
    const long m0 = (long)blockIdx.y * BM;
    const int  n0 = blockIdx.x * BN;

    uint32_t sb;
    asm("{ .reg .u64 t; cvta.to.shared.u64 t, %1; cvt.u32.u64 %0, t; }"
        : "=r"(sb) : "l"(sm));

    // bias cache (128 bf16 at offset STAGES*STAGE_BYTES)
    __nv_bfloat16* biasSm = reinterpret_cast<__nv_bfloat16*>(sm + STAGES * STAGE_BYTES);
    if (tid < 64)
        reinterpret_cast<uint32_t*>(biasSm)[tid] =
            reinterpret_cast<const uint32_t*>(g_bias + n0)[tid];

    // stage loader: A tile rows m0..m0+127, B tile rows n0..n0+127, cols k0..k0+63
    auto load_stage = [&](int s, int k0) {
#pragma unroll
        for (int c = tid; c < 1024; c += 256) {
            int isB = c >> 9;
            int cc  = c & 511;
            int row = cc >> 2;
            int seg = cc & 3;
            const unsigned char* g = isB
                ? wq + (size_t)(n0 + row) * KDIM + k0 + seg * 16
                : xq + (size_t)(m0 + row) * KDIM + k0 + seg * 16;
            uint32_t d = sb + (uint32_t)s * STAGE_BYTES + (uint32_t)isB * OP_BYTES
                       + (uint32_t)row * ASTRIDE + (uint32_t)seg * 16;
            cpasync16(d, g);
        }
    };

    float acc[2][8][4];
#pragma unroll
    for (int mt = 0; mt < 2; mt++)
#pragma unroll
        for (int nt = 0; nt < 8; nt++)
#pragma unroll
            for (int j = 0; j < 4; j++) acc[mt][nt][j] = 0.0f;

    // prologue: stages 0..PREFETCH-1
#pragma unroll
    for (int s = 0; s < PREFETCH; s++) {
        load_stage(s, s * BK);
        asm volatile("cp.async.commit_group;\n" ::: "memory");
    }

    // ldmatrix per-lane address offsets (within an operand tile)
    const int lt = lane >> 3;          // ldmatrix tile index 0..3
    const int lr = lane & 7;           // row within 8-row tile
    // A (mt): tiles = (rowblk lt&1, kchunk lt>>1)
    uint32_t aoff[2];
#pragma unroll
    for (int mt = 0; mt < 2; mt++)
        aoff[mt] = (uint32_t)(mw * 32 + mt * 16 + (lt & 1) * 8 + lr) * ASTRIDE
                 + (uint32_t)(lt >> 1) * 16;
    // B (pair j -> nt=2j+(lt>>1)): tiles = (ntblk lt>>1, kchunk lt&1)
    uint32_t boff[4];
#pragma unroll
    for (int j = 0; j < 4; j++)
        boff[j] = (uint32_t)(nw * 64 + (2 * j + (lt >> 1)) * 8 + lr) * ASTRIDE
                + (uint32_t)(lt & 1) * 16;

#pragma unroll 1
    for (int kt = 0; kt < KTILES; kt++) {
        asm volatile("cp.async.wait_group %0;\n" :: "n"(PREFETCH - 1) : "memory");
        __syncthreads();

        int kn = kt + PREFETCH;
        if (kn < KTILES) load_stage(kn & (STAGES - 1), kn * BK);
        asm volatile("cp.async.commit_group;\n" ::: "memory");

        const uint32_t aBase = sb + (uint32_t)(kt & (STAGES - 1)) * STAGE_BYTES;
        const uint32_t bBase = aBase + OP_BYTES;

#pragma unroll
        for (int ks = 0; ks < 2; ks++) {
            const uint32_t kb = ks * 32;
            uint32_t a[2][4];
            ldsm_x4(aBase + aoff[0] + kb, a[0][0], a[0][1], a[0][2], a[0][3]);
            ldsm_x4(aBase + aoff[1] + kb, a[1][0], a[1][1], a[1][2], a[1][3]);
            uint32_t b[8][2];
#pragma unroll
            for (int j = 0; j < 4; j++) {
                ldsm_x4(bBase + boff[j] + kb,
                        b[2 * j][0], b[2 * j][1], b[2 * j + 1][0], b[2 * j + 1][1]);
            }
#pragma unroll
            for (int nt = 0; nt < 8; nt++) {
                mma_e4m3(acc[0][nt], a[0], b[nt][0], b[nt][1]);
                mma_e4m3(acc[1][nt], a[1], b[nt][0], b[nt][1]);
            }
        }
    }

    // -------- epilogue: scale, bf16 round, +bias (bf16 add), widen to f32 ----
    float xs = fmaxf(__uint_as_float(g_amax[0]), 1e-6f);
    float ws = fmaxf(__uint_as_float(g_amax[1]), 1e-6f);
    float sc = xs * ws;

#pragma unroll
    for (int mt = 0; mt < 2; mt++) {
        long r0 = m0 + mw * 32 + mt * 16 + (lane >> 2);
#pragma unroll
        for (int nt = 0; nt < 8; nt++) {
            int cn = nw * 64 + nt * 8 + (lane & 3) * 2;  // local col in [0,128)
            long g0 = r0 * NDIM + n0 + cn;
            long g1 = (r0 + 8) * NDIM + n0 + cn;
            __nv_bfloat16 v00 = __hadd(__float2bfloat16(acc[mt][nt][0] * sc), biasSm[cn]);
            __nv_bfloat16 v01 = __hadd(__float2bfloat16(acc[mt][nt][1] * sc), biasSm[cn + 1]);
            __nv_bfloat16 v10 = __hadd(__float2bfloat16(acc[mt][nt][2] * sc), biasSm[cn]);
            __nv_bfloat16 v11 = __hadd(__float2bfloat16(acc[mt][nt][3] * sc), biasSm[cn + 1]);
            float2 f0 = make_float2(__bfloat162float(v00), __bfloat162float(v01));
            float2 f1 = make_float2(__bfloat162float(v10), __bfloat162float(v11));
            *reinterpret_cast<float2*>(out + g0) = f0;
            *reinterpret_cast<float2*>(out + g1) = f1;
        }
    }
}

// -------------------- host side -------------------------------------------
extern "C" void kernel_launch(void* const* d_in, const int* in_sizes, int n_in,
                              void* d_out, int out_size) {
    // Resolve inputs BY SIZE (element counts): x=M*K, weight=N*K, bias=N.
    // All buffers are FLOAT32 (bf16 values widened by the harness).
    const float* x = nullptr;
    const float* w = nullptr;
    const float* bias = nullptr;
    for (int i = 0; i < n_in; i++) {
        long sz = in_sizes[i];
        if (sz == MDIM * KDIM)      x    = (const float*)d_in[i];
        else if (sz == NDIM * KDIM) w    = (const float*)d_in[i];
        else if (sz == NDIM)        bias = (const float*)d_in[i];
    }
    float* out = (float*)d_out;

    void *xq = nullptr, *wq = nullptr;
    cudaGetSymbolAddress(&xq, g_xq);
    cudaGetSymbolAddress(&wq, g_wq);

    // 1) reset
    reset_kernel<<<1, 1>>>();
    // 2) amax (f32 reads)
    amax_f32<<<2048, 256>>>((const uint4*)x, MDIM * KDIM / 4, 0);
    amax_f32<<<512, 256>>>((const uint4*)w, NDIM * KDIM / 4, 1);
    // 3) quantize f32 -> e4m3 scratch (16B stores)
    quant_f32<<<4096, 256>>>((const uint4*)x, (uint4*)xq, MDIM * KDIM, 0);
    quant_f32<<<1024, 256>>>((const uint4*)w, (uint4*)wq, NDIM * KDIM, 1);
    // 4) bias staging (f32 -> bf16, exact)
    bias_prep<<<2, 1024>>>(bias);

    // 5) GEMM (mma.sync fp8 + ldmatrix; f32 output)
    cudaFuncSetAttribute(gemm_kernel, cudaFuncAttributeMaxDynamicSharedMemorySize,
                         SMEM_BYTES);
    dim3 grid((unsigned)(NDIM / BN), (unsigned)(MDIM / BM), 1);
    gemm_kernel<<<grid, 256, SMEM_BYTES>>>(
        (const unsigned char*)xq, (const unsigned char*)wq, out);
}